// round 1
// baseline (speedup 1.0000x reference)
#include <cuda_runtime.h>

// Census loss, pair-symmetric formulation.
// total = sum_{a in image} sum_{off in H(24)} t(a,off) * (v(a) + v(a+off))
// where t = e^2/(0.1+e^2), e = cx - cy, c* = d/sqrt(0.81+d^2), d = g(a+off)-g(a),
// v(p) = 1 iff p is >=3 pixels from every border. Output = total / (49*B*H*W).

#define TILE 32
#define HALO 3
#define SW   (TILE + 2 * HALO)   // 38
#define IMG  256
#define IMG2 (IMG * IMG)         // 65536

__device__ __forceinline__ float frsqrt_a(float x) {
    float r;
    asm("rsqrt.approx.f32 %0, %1;" : "=f"(r) : "f"(x));
    return r;
}
__device__ __forceinline__ float frcp_a(float x) {
    float r;
    asm("rcp.approx.f32 %0, %1;" : "=f"(r) : "f"(x));
    return r;
}

__global__ __launch_bounds__(256, 4)
void census_loss_kernel(const float* __restrict__ x,
                        const float* __restrict__ y,
                        float* __restrict__ out)
{
    __shared__ float sgx[SW * SW];
    __shared__ float sgy[SW * SW];

    const int b    = blockIdx.z;
    const int row0 = blockIdx.y * TILE;
    const int col0 = blockIdx.x * TILE;
    const int tid  = threadIdx.y * 32 + threadIdx.x;

    const float* xb = x + (size_t)b * 3 * IMG2;
    const float* yb = y + (size_t)b * 3 * IMG2;

    // Load grayscale tile + halo (zero-fill outside image; weight=0 kills those pairs)
    for (int i = tid; i < SW * SW; i += 256) {
        int lr = i / SW;
        int lc = i - lr * SW;
        int gr = row0 - HALO + lr;
        int gc = col0 - HALO + lc;
        float gx = 0.f, gy = 0.f;
        if ((unsigned)gr < (unsigned)IMG && (unsigned)gc < (unsigned)IMG) {
            int o = gr * IMG + gc;
            gx = (xb[o] + xb[o + IMG2] + xb[o + 2 * IMG2]) * (1.f / 3.f);
            gy = (yb[o] + yb[o + IMG2] + yb[o + 2 * IMG2]) * (1.f / 3.f);
        }
        sgx[i] = gx;
        sgy[i] = gy;
    }
    __syncthreads();

    const int tx   = threadIdx.x;
    const int gcol = col0 + tx;

    // Column validity for dx = -3..3 (valid cols are [3,252])
    float vcol[7];
#pragma unroll
    for (int d = 0; d < 7; d++)
        vcol[d] = ((unsigned)(gcol + d - 6) < 250u) ? 1.f : 0.f;

    float acc = 0.f;

#pragma unroll 1
    for (int k = 0; k < 4; k++) {
        const int lrow = threadIdx.y + 8 * k;    // 0..31
        const int grow = row0 + lrow;

        float vrow[4];
#pragma unroll
        for (int d = 0; d < 4; d++)
            vrow[d] = ((unsigned)(grow + d - 3) < 250u) ? 1.f : 0.f;
        const float va = vrow[0] * vcol[3];      // validity of center

        const float* px = &sgx[(lrow + HALO) * SW + tx + HALO];
        const float* py = &sgy[(lrow + HALO) * SW + tx + HALO];
        const float gax = px[0];
        const float gay = py[0];

#pragma unroll
        for (int dy = 0; dy < 4; dy++) {
#pragma unroll
            for (int dx = -3; dx <= 3; dx++) {
                if (dy == 0 && dx <= 0) continue;   // half-offset set H (24 offsets)
                float gbx = px[dy * SW + dx];
                float gby = py[dy * SW + dx];
                float dX = gbx - gax;
                float dY = gby - gay;
                float cx = dX * frsqrt_a(fmaf(dX, dX, 0.81f));
                float cy = dY * frsqrt_a(fmaf(dY, dY, 0.81f));
                float e  = cx - cy;
                float e2 = e * e;
                float t  = e2 * frcp_a(e2 + 0.1f);
                float w  = fmaf(vrow[dy], vcol[dx + 3], va);  // v(a)+v(b)
                acc = fmaf(t, w, acc);
            }
        }
    }

    // Warp reduction (warp == one ty row)
#pragma unroll
    for (int s = 16; s > 0; s >>= 1)
        acc += __shfl_xor_sync(0xFFFFFFFFu, acc, s);

    __shared__ float wsum[8];
    if ((tid & 31) == 0) wsum[tid >> 5] = acc;
    __syncthreads();
    if (tid < 8) {
        float v = wsum[tid];
#pragma unroll
        for (int s = 4; s > 0; s >>= 1)
            v += __shfl_xor_sync(0xFFu, v, s);
        if (tid == 0) {
            // scale: 1 / (49 * 8 * 256 * 256)
            atomicAdd(out, v * (1.f / 25690112.f));
        }
    }
}

extern "C" void kernel_launch(void* const* d_in, const int* in_sizes, int n_in,
                              void* d_out, int out_size)
{
    const float* x = (const float*)d_in[0];
    const float* y = (const float*)d_in[1];
    float* out = (float*)d_out;

    cudaMemsetAsync(out, 0, sizeof(float));

    dim3 block(32, 8, 1);
    dim3 grid(IMG / TILE, IMG / TILE, 8);   // 8 x 8 x 8 = 512 blocks
    census_loss_kernel<<<grid, block>>>(x, y, out);
}

// round 2
// speedup vs baseline: 1.1228x; 1.1228x over previous
#include <cuda_runtime.h>

// Census loss, pair-symmetric, f32x2-packed (2 horizontally-adjacent pixels/thread).
// total = sum_{a} sum_{off in H(24)} t(a,off) * (v(a)+v(a+off)),
// t = e^2/(0.1+e^2), e = cx-cy, c = d*rsqrt(0.81+d^2), d = g(a+off)-g(a).
// Interior blocks (all weights == 2) skip weight math entirely.

#define IMG   256
#define IMG2  65536
#define TCOLS 32
#define TROWS 16
#define SW    38   // TCOLS + 6
#define SWR   22   // TROWS + 6
#define SW2   19   // SW/2 in float2

typedef unsigned long long ull;

__device__ __forceinline__ float frsqrt_a(float x){ float r; asm("rsqrt.approx.f32 %0, %1;" : "=f"(r) : "f"(x)); return r; }
__device__ __forceinline__ float frcp_a  (float x){ float r; asm("rcp.approx.f32 %0, %1;"   : "=f"(r) : "f"(x)); return r; }

__device__ __forceinline__ ull pk(float lo, float hi){ ull r; asm("mov.b64 %0, {%1, %2};" : "=l"(r) : "f"(lo), "f"(hi)); return r; }
__device__ __forceinline__ float2 upk(ull v){ float2 f; asm("mov.b64 {%0, %1}, %2;" : "=f"(f.x), "=f"(f.y) : "l"(v)); return f; }
__device__ __forceinline__ ull fma2(ull a, ull b, ull c){ ull r; asm("fma.rn.f32x2 %0, %1, %2, %3;" : "=l"(r) : "l"(a), "l"(b), "l"(c)); return r; }
__device__ __forceinline__ ull add2(ull a, ull b){ ull r; asm("add.rn.f32x2 %0, %1, %2;" : "=l"(r) : "l"(a), "l"(b)); return r; }
__device__ __forceinline__ ull mul2(ull a, ull b){ ull r; asm("mul.rn.f32x2 %0, %1, %2;" : "=l"(r) : "l"(a), "l"(b)); return r; }

// packed t = e^2/(0.1+e^2) for two pixels at once
__device__ __forceinline__ ull pair_t(ull nbx, ull nby, ull cenx, ull ceny,
                                      ull NEG1, ull C081, ull C01)
{
    ull dX = fma2(cenx, NEG1, nbx);          // nb - cen
    ull dY = fma2(ceny, NEG1, nby);
    ull aX = fma2(dX, dX, C081);
    ull aY = fma2(dY, dY, C081);
    float2 a = upk(aX);
    ull rX = pk(frsqrt_a(a.x), frsqrt_a(a.y));
    float2 b = upk(aY);
    ull rY = pk(frsqrt_a(b.x), frsqrt_a(b.y));
    ull cx = mul2(dX, rX);
    ull cy = mul2(dY, rY);
    ull e  = fma2(cy, NEG1, cx);
    ull e2 = mul2(e, e);
    ull dn = add2(e2, C01);
    float2 d = upk(dn);
    ull rc = pk(frcp_a(d.x), frcp_a(d.y));
    return mul2(e2, rc);
}

template<bool BORDER>
__device__ __forceinline__ ull accum(ull acc, ull t, int dy, int dx,
                                     const float* vrow, const float* vcw,
                                     float va0, float va1)
{
    if (!BORDER) return add2(acc, t);
    float w0 = fmaf(vrow[dy], vcw[dx + 3], va0);   // v(a0)+v(b0)
    float w1 = fmaf(vrow[dy], vcw[dx + 4], va1);
    return fma2(t, pk(w0, w1), acc);
}

template<bool BORDER>
__device__ __forceinline__ float census_body(const float2* __restrict__ px0,
                                             const float2* __restrict__ py0,
                                             int r, int c0)
{
    const ull NEG1 = pk(-1.f, -1.f);
    const ull C081 = pk(0.81f, 0.81f);
    const ull C01  = pk(0.1f, 0.1f);

    float vrow[4], vcw[8];
    float va0 = 0.f, va1 = 0.f;
    if (BORDER) {
#pragma unroll
        for (int d = 0; d < 4; d++) vrow[d] = ((unsigned)(r + d - 3) < 250u) ? 1.f : 0.f;
#pragma unroll
        for (int j = 0; j < 8; j++) vcw[j] = ((unsigned)(c0 - 6 + j) < 250u) ? 1.f : 0.f;
        va0 = vrow[0] * vcw[3];
        va1 = vrow[0] * vcw[4];
    }

    ull acc = 0ULL;   // {+0,+0}

    // center row (dy = 0): window cols 2..7 (float2 elems 1..3)
    float2 x1 = px0[1], x2 = px0[2], x3 = px0[3];
    float2 y1 = py0[1], y2 = py0[2], y3 = py0[3];
    const ull cenx = pk(x1.y, x2.x);
    const ull ceny = pk(y1.y, y2.x);

    {   // dx = 1: cols (4,5)
        ull t = pair_t(pk(x2.x, x2.y), pk(y2.x, y2.y), cenx, ceny, NEG1, C081, C01);
        acc = accum<BORDER>(acc, t, 0, 1, vrow, vcw, va0, va1);
    }
    {   // dx = 2: cols (5,6)
        ull t = pair_t(pk(x2.y, x3.x), pk(y2.y, y3.x), cenx, ceny, NEG1, C081, C01);
        acc = accum<BORDER>(acc, t, 0, 2, vrow, vcw, va0, va1);
    }
    {   // dx = 3: cols (6,7)
        ull t = pair_t(pk(x3.x, x3.y), pk(y3.x, y3.y), cenx, ceny, NEG1, C081, C01);
        acc = accum<BORDER>(acc, t, 0, 3, vrow, vcw, va0, va1);
    }

#pragma unroll
    for (int dy = 1; dy < 4; dy++) {
        const float2* prx = px0 + dy * SW2;
        const float2* pry = py0 + dy * SW2;
        float2 a0 = prx[0], a1 = prx[1], a2 = prx[2], a3 = prx[3];
        float2 b0 = pry[0], b1 = pry[1], b2 = pry[2], b3 = pry[3];

        // neighbor pair for dx = cols (3+dx, 4+dx) of window a0..a3
        {   ull t = pair_t(pk(a0.x, a0.y), pk(b0.x, b0.y), cenx, ceny, NEG1, C081, C01);
            acc = accum<BORDER>(acc, t, dy, -3, vrow, vcw, va0, va1); }
        {   ull t = pair_t(pk(a0.y, a1.x), pk(b0.y, b1.x), cenx, ceny, NEG1, C081, C01);
            acc = accum<BORDER>(acc, t, dy, -2, vrow, vcw, va0, va1); }
        {   ull t = pair_t(pk(a1.x, a1.y), pk(b1.x, b1.y), cenx, ceny, NEG1, C081, C01);
            acc = accum<BORDER>(acc, t, dy, -1, vrow, vcw, va0, va1); }
        {   ull t = pair_t(pk(a1.y, a2.x), pk(b1.y, b2.x), cenx, ceny, NEG1, C081, C01);
            acc = accum<BORDER>(acc, t, dy,  0, vrow, vcw, va0, va1); }
        {   ull t = pair_t(pk(a2.x, a2.y), pk(b2.x, b2.y), cenx, ceny, NEG1, C081, C01);
            acc = accum<BORDER>(acc, t, dy,  1, vrow, vcw, va0, va1); }
        {   ull t = pair_t(pk(a2.y, a3.x), pk(b2.y, b3.x), cenx, ceny, NEG1, C081, C01);
            acc = accum<BORDER>(acc, t, dy,  2, vrow, vcw, va0, va1); }
        {   ull t = pair_t(pk(a3.x, a3.y), pk(b3.x, b3.y), cenx, ceny, NEG1, C081, C01);
            acc = accum<BORDER>(acc, t, dy,  3, vrow, vcw, va0, va1); }
    }

    float2 s = upk(acc);
    float r2 = s.x + s.y;
    return BORDER ? r2 : r2 * 2.f;   // interior: all weights == 2
}

__global__ __launch_bounds__(256, 4)
void census_loss_kernel(const float* __restrict__ x,
                        const float* __restrict__ y,
                        float* __restrict__ out)
{
    __shared__ __align__(16) float sgx[SWR * SW];
    __shared__ __align__(16) float sgy[SWR * SW];

    const int b    = blockIdx.z;
    const int row0 = blockIdx.y * TROWS;
    const int col0 = blockIdx.x * TCOLS;
    const int tid  = threadIdx.y * 16 + threadIdx.x;

    const float* xb = x + (size_t)b * 3 * IMG2;
    const float* yb = y + (size_t)b * 3 * IMG2;

    // grayscale tile + halo (zero outside image; weight 0 kills those pairs)
    for (int i = tid; i < SWR * SW; i += 256) {
        int lr = i / SW;
        int lc = i - lr * SW;
        int gr = row0 - 3 + lr;
        int gc = col0 - 3 + lc;
        float gx = 0.f, gy = 0.f;
        if ((unsigned)gr < (unsigned)IMG && (unsigned)gc < (unsigned)IMG) {
            int o = gr * IMG + gc;
            gx = (xb[o] + xb[o + IMG2] + xb[o + 2 * IMG2]) * (1.f / 3.f);
            gy = (yb[o] + yb[o + IMG2] + yb[o + 2 * IMG2]) * (1.f / 3.f);
        }
        sgx[i] = gx;
        sgy[i] = gy;
    }
    __syncthreads();

    const int tx = threadIdx.x;          // 0..15
    const int ty = threadIdx.y;          // 0..15
    const int baseoff = (ty + 3) * SW + 2 * tx;   // even -> 8B aligned
    const float2* px0 = (const float2*)(sgx + baseoff);
    const float2* py0 = (const float2*)(sgy + baseoff);

    const int r  = row0 + ty;
    const int c0 = col0 + 2 * tx;

    const bool interior = (blockIdx.x >= 1) & (blockIdx.x <= 6) &
                          (blockIdx.y >= 1) & (blockIdx.y <= 14);

    float acc = interior ? census_body<false>(px0, py0, r, c0)
                         : census_body<true >(px0, py0, r, c0);

    // warp + block reduction
#pragma unroll
    for (int s = 16; s > 0; s >>= 1)
        acc += __shfl_xor_sync(0xFFFFFFFFu, acc, s);

    __shared__ float wsum[8];
    if ((tid & 31) == 0) wsum[tid >> 5] = acc;
    __syncthreads();
    if (tid < 8) {
        float v = wsum[tid];
#pragma unroll
        for (int s = 4; s > 0; s >>= 1)
            v += __shfl_xor_sync(0xFFu, v, s);
        if (tid == 0)
            atomicAdd(out, v * (1.f / 25690112.f));   // 1/(49*8*256*256)
    }
}

extern "C" void kernel_launch(void* const* d_in, const int* in_sizes, int n_in,
                              void* d_out, int out_size)
{
    const float* x = (const float*)d_in[0];
    const float* y = (const float*)d_in[1];
    float* out = (float*)d_out;

    cudaMemsetAsync(out, 0, sizeof(float));

    dim3 block(16, 16, 1);
    dim3 grid(IMG / TCOLS, IMG / TROWS, 8);   // 8 x 16 x 8 = 1024 blocks
    census_loss_kernel<<<grid, block>>>(x, y, out);
}